// round 4
// baseline (speedup 1.0000x reference)
#include <cuda_runtime.h>
#include <cstdint>

typedef unsigned long long ull;

// Problem constants
#define B_   64
#define T_   1024
#define IN_  512
#define H_   512
#define G4H  2048
#define M_   (B_ * T_)                 // 65536 rows for the input GEMM
#define YSZ  ((size_t)B_ * T_ * H_)    // 33554432 y1 elements
#define HB   (H_ * B_)                 // 32768

// -------- scratch (static device globals; no allocation allowed) ----------
__device__ float g_xz[(size_t)M_ * G4H];   // xz for current layer [B,T,4H]
__device__ float g_y0[(size_t)M_ * H_];    // layer-0 output [B,T,H]
__device__ float g_h[2][2][HB];            // [layer][slot][k*64+m], h TRANSPOSED [H][B]
__device__ unsigned g_bar;                 // grid barrier counter

// -------- packed f32x2 helpers (Blackwell dual-fp32 pipe) -----------------
__device__ __forceinline__ ull ffma2(ull a, ull b, ull c) {
    ull d;
    asm("fma.rn.f32x2 %0, %1, %2, %3;" : "=l"(d) : "l"(a), "l"(b), "l"(c));
    return d;
}
__device__ __forceinline__ ull dup2(float x) {
    ull d;
    asm("mov.b64 %0, {%1, %1};" : "=l"(d) : "f"(x));
    return d;
}
__device__ __forceinline__ float2 unpk(ull v) {
    float lo, hi;
    asm("mov.b64 {%0, %1}, %2;" : "=f"(lo), "=f"(hi) : "l"(v));
    return make_float2(lo, hi);
}
// L2-coherent 16B load (bypass L1: h slots are rewritten by other SMs)
__device__ __forceinline__ void ldcg_u64x2(const void* p, ull& a, ull& b) {
    asm volatile("ld.global.cg.v2.u64 {%0, %1}, [%2];"
                 : "=l"(a), "=l"(b) : "l"(p));
}

// ===================== input-projection GEMM ==============================
// C[M,2048] = A[M,512] * W[512,2048]
#define BM 128
#define BN 64
#define BK 16

__global__ __launch_bounds__(256) void gemm_xw(const float* __restrict__ A,
                                               const float* __restrict__ W,
                                               float* __restrict__ C) {
    __shared__ float As[BK * BM];   // transposed A tile: As[k][m]
    __shared__ float Bs[BK * BN];   // Bs[k][n]

    const int tid = threadIdx.x;
    const int tx = tid & 15;
    const int ty = tid >> 4;
    const int m0 = ty * 8;
    const int n0 = tx * 4;
    const long gm0 = (long)blockIdx.y * BM;
    const int  gn0 = blockIdx.x * BN;

    ull acc[4][4];
#pragma unroll
    for (int i = 0; i < 4; i++)
#pragma unroll
        for (int j = 0; j < 4; j++) acc[i][j] = 0ull;

    for (int k0 = 0; k0 < 512; k0 += BK) {
        __syncthreads();
#pragma unroll
        for (int j = 0; j < 2; j++) {
            int q  = tid * 2 + j;
            int r  = q >> 2;
            int kq = q & 3;
            float4 v = *(const float4*)(A + (gm0 + r) * 512 + k0 + kq * 4);
            As[(kq * 4 + 0) * BM + r] = v.x;
            As[(kq * 4 + 1) * BM + r] = v.y;
            As[(kq * 4 + 2) * BM + r] = v.z;
            As[(kq * 4 + 3) * BM + r] = v.w;
        }
        {
            int kr = tid >> 4;
            int nq = tid & 15;
            *(float4*)(Bs + kr * BN + nq * 4) =
                *(const float4*)(W + (long)(k0 + kr) * G4H + gn0 + nq * 4);
        }
        __syncthreads();

#pragma unroll
        for (int kk = 0; kk < BK; kk++) {
            const ull* ap = (const ull*)(As + kk * BM + m0);
            ull a0 = ap[0], a1 = ap[1], a2 = ap[2], a3 = ap[3];
            float4 b = *(const float4*)(Bs + kk * BN + n0);
            ull b0 = dup2(b.x), b1 = dup2(b.y), b2 = dup2(b.z), b3 = dup2(b.w);
            acc[0][0] = ffma2(a0, b0, acc[0][0]);
            acc[0][1] = ffma2(a0, b1, acc[0][1]);
            acc[0][2] = ffma2(a0, b2, acc[0][2]);
            acc[0][3] = ffma2(a0, b3, acc[0][3]);
            acc[1][0] = ffma2(a1, b0, acc[1][0]);
            acc[1][1] = ffma2(a1, b1, acc[1][1]);
            acc[1][2] = ffma2(a1, b2, acc[1][2]);
            acc[1][3] = ffma2(a1, b3, acc[1][3]);
            acc[2][0] = ffma2(a2, b0, acc[2][0]);
            acc[2][1] = ffma2(a2, b1, acc[2][1]);
            acc[2][2] = ffma2(a2, b2, acc[2][2]);
            acc[2][3] = ffma2(a2, b3, acc[2][3]);
            acc[3][0] = ffma2(a3, b0, acc[3][0]);
            acc[3][1] = ffma2(a3, b1, acc[3][1]);
            acc[3][2] = ffma2(a3, b2, acc[3][2]);
            acc[3][3] = ffma2(a3, b3, acc[3][3]);
        }
    }

#pragma unroll
    for (int mp = 0; mp < 4; mp++) {
#pragma unroll
        for (int c = 0; c < 4; c++) {
            float2 v = unpk(acc[mp][c]);
            long row = gm0 + m0 + 2 * mp;
            C[row * G4H + gn0 + n0 + c]       = v.x;
            C[(row + 1) * G4H + gn0 + n0 + c] = v.y;
        }
    }
}

// ===================== persistent LSTM layer ==============================
// 128 CTAs (1 per SM, all co-resident) x 256 threads. CTA j owns hidden
// units [4j,4j+4) = 16 gate columns. Thread GEMM tile = 16 cols x 4 batch
// rows, 16-way K split. h read straight from global L2 (ld.cg), Wh slice
// cached in SMEM pre-duplicated as f32x2, c-state in registers.
#define PBS   66                                  // padded pbuf row stride
#define WD_BYTES (512 * 16 * 8)                   // 65536
#define PB_BYTES (16 * 16 * PBS * 4)              // 67584
#define LSM_BYTES (WD_BYTES + PB_BYTES)           // 133120
#define NCTA 128

__device__ __forceinline__ void grid_bar(unsigned target) {
    __syncthreads();
    if (threadIdx.x == 0) {
        __threadfence();                 // release h writes to GPU scope
        atomicAdd(&g_bar, 1u);
        unsigned v;
        do {
            asm volatile("ld.acquire.gpu.global.u32 %0, [%1];"
                         : "=r"(v) : "l"(&g_bar) : "memory");
        } while (v < target);
    }
    __syncthreads();
}

__global__ __launch_bounds__(256, 1) void lstm_layer(
    const float* __restrict__ xz,     // [B,T,4H]
    const float* __restrict__ Wh,     // [512,2048]
    const float* __restrict__ bias,   // [2048]
    float* __restrict__ hs0,          // h slot 0, [H][B]
    float* __restrict__ hs1,          // h slot 1, [H][B]
    float* __restrict__ y,            // [B,T,H]
    float* __restrict__ hfin,         // [B,H]
    float* __restrict__ cfin)         // [B,H]
{
    extern __shared__ char smem[];
    ull*   wdup = (ull*)smem;                   // [512][16] duplicated Wh cols
    float* pbuf = (float*)(smem + WD_BYTES);    // [16 ks][16 c][PBS]

    const int tid = threadIdx.x;
    const int hu0 = blockIdx.x * 4;

    // ---- one-time: load this CTA's Wh slice, duplicated for f32x2 ----
    for (int idx = tid; idx < 512 * 16; idx += 256) {
        int k = idx >> 4, c = idx & 15;
        wdup[idx] = dup2(Wh[(long)k * G4H + (c >> 2) * 512 + hu0 + (c & 3)]);
    }

    // ---- roles ----
    const int mg = tid & 15;         // GEMM: 16 m-groups of 4 rows
    const int ks = tid >> 4;         // GEMM: 16-way K split (32 k each)
    const int m0 = mg * 4;
    const int m  = tid >> 2;         // gate pass: batch row
    const int u  = tid & 3;          // gate pass: local unit

    const float bi = bias[hu0 + u];
    const float bf = bias[512 + hu0 + u];
    const float bg = bias[1024 + hu0 + u];
    const float bo = bias[1536 + hu0 + u];
    float creg = 0.f;
    const float* xzp = xz + (size_t)m * T_ * G4H + hu0 + u;

    float* hslot[2] = { hs0, hs1 };
    __syncthreads();

    for (int t = 0; t < T_; t++) {
        // prefetch xz for this step (independent of h; hides DRAM latency)
        const float* xp = xzp + (size_t)t * G4H;
        float x_i = xp[0], x_f = xp[512], x_g = xp[1024], x_o = xp[1536];

        ull acc[2][16];
#pragma unroll
        for (int c = 0; c < 16; c++) { acc[0][c] = 0ull; acc[1][c] = 0ull; }

        if (t > 0) {
            const float* hin = hslot[(t + 1) & 1];   // slot written at t-1
            const float* hp  = hin + (ks * 32) * 64 + m0;
            const ull*   wr  = wdup + (ks * 32) * 16;
#pragma unroll 2
            for (int k = 0; k < 32; k++) {
                ull h01, h23;
                ldcg_u64x2(hp, h01, h23);            // 4 batch vals, 2 pairs
                hp += 64;
                ulonglong2 w01 = ((const ulonglong2*)wr)[0];
                ulonglong2 w23 = ((const ulonglong2*)wr)[1];
                ulonglong2 w45 = ((const ulonglong2*)wr)[2];
                ulonglong2 w67 = ((const ulonglong2*)wr)[3];
                ulonglong2 w89 = ((const ulonglong2*)wr)[4];
                ulonglong2 wab = ((const ulonglong2*)wr)[5];
                ulonglong2 wcd = ((const ulonglong2*)wr)[6];
                ulonglong2 wef = ((const ulonglong2*)wr)[7];
                wr += 16;
                acc[0][0]  = ffma2(h01, w01.x, acc[0][0]);
                acc[1][0]  = ffma2(h23, w01.x, acc[1][0]);
                acc[0][1]  = ffma2(h01, w01.y, acc[0][1]);
                acc[1][1]  = ffma2(h23, w01.y, acc[1][1]);
                acc[0][2]  = ffma2(h01, w23.x, acc[0][2]);
                acc[1][2]  = ffma2(h23, w23.x, acc[1][2]);
                acc[0][3]  = ffma2(h01, w23.y, acc[0][3]);
                acc[1][3]  = ffma2(h23, w23.y, acc[1][3]);
                acc[0][4]  = ffma2(h01, w45.x, acc[0][4]);
                acc[1][4]  = ffma2(h23, w45.x, acc[1][4]);
                acc[0][5]  = ffma2(h01, w45.y, acc[0][5]);
                acc[1][5]  = ffma2(h23, w45.y, acc[1][5]);
                acc[0][6]  = ffma2(h01, w67.x, acc[0][6]);
                acc[1][6]  = ffma2(h23, w67.x, acc[1][6]);
                acc[0][7]  = ffma2(h01, w67.y, acc[0][7]);
                acc[1][7]  = ffma2(h23, w67.y, acc[1][7]);
                acc[0][8]  = ffma2(h01, w89.x, acc[0][8]);
                acc[1][8]  = ffma2(h23, w89.x, acc[1][8]);
                acc[0][9]  = ffma2(h01, w89.y, acc[0][9]);
                acc[1][9]  = ffma2(h23, w89.y, acc[1][9]);
                acc[0][10] = ffma2(h01, wab.x, acc[0][10]);
                acc[1][10] = ffma2(h23, wab.x, acc[1][10]);
                acc[0][11] = ffma2(h01, wab.y, acc[0][11]);
                acc[1][11] = ffma2(h23, wab.y, acc[1][11]);
                acc[0][12] = ffma2(h01, wcd.x, acc[0][12]);
                acc[1][12] = ffma2(h23, wcd.x, acc[1][12]);
                acc[0][13] = ffma2(h01, wcd.y, acc[0][13]);
                acc[1][13] = ffma2(h23, wcd.y, acc[1][13]);
                acc[0][14] = ffma2(h01, wef.x, acc[0][14]);
                acc[1][14] = ffma2(h23, wef.x, acc[1][14]);
                acc[0][15] = ffma2(h01, wef.y, acc[0][15]);
                acc[1][15] = ffma2(h23, wef.y, acc[1][15]);
            }
        }

        __syncthreads();   // previous step's pbuf reads are done
#pragma unroll
        for (int c = 0; c < 16; c++) {
            *(ull*)&pbuf[(ks * 16 + c) * PBS + m0]     = acc[0][c];
            *(ull*)&pbuf[(ks * 16 + c) * PBS + m0 + 2] = acc[1][c];
        }
        __syncthreads();

        // ---- K-split reduction + gates (thread = (m, u)) ----
        float zi = bi + x_i, zf = bf + x_f, zg = bg + x_g, zo = bo + x_o;
#pragma unroll
        for (int s = 0; s < 16; s++) {
            const float* pr = pbuf + (s * 16 + u) * PBS + m;
            zi += pr[0];
            zf += pr[4 * PBS];
            zg += pr[8 * PBS];
            zo += pr[12 * PBS];
        }

        float ig  = 1.f / (1.f + __expf(-zi));
        float fg  = 1.f / (1.f + __expf(-zf));
        float gg  = tanhf(zg);
        float ogt = 1.f / (1.f + __expf(-zo));

        creg = fg * creg + ig * gg;
        float hn = ogt * tanhf(creg);

        hslot[t & 1][(hu0 + u) * 64 + m] = hn;
        y[((size_t)m * T_ + t) * H_ + hu0 + u] = hn;

        if (t == T_ - 1) {
            hfin[m * H_ + hu0 + u] = hn;
            cfin[m * H_ + hu0 + u] = creg;
        } else {
            grid_bar((unsigned)(t + 1) * NCTA);
        }
    }
}

// ===================== barrier reset ======================================
__global__ void reset_bar() { g_bar = 0; }

// ===================== launch =============================================
extern "C" void kernel_launch(void* const* d_in, const int* in_sizes, int n_in,
                              void* d_out, int out_size) {
    const float* x   = (const float*)d_in[0];
    const float* Wx0 = (const float*)d_in[1];
    const float* Wh0 = (const float*)d_in[2];
    const float* b0  = (const float*)d_in[3];
    const float* Wx1 = (const float*)d_in[4];
    const float* Wh1 = (const float*)d_in[5];
    const float* b1  = (const float*)d_in[6];
    float* out = (float*)d_out;

    float *xz, *y0, *hb;
    cudaGetSymbolAddress((void**)&xz, g_xz);
    cudaGetSymbolAddress((void**)&y0, g_y0);
    cudaGetSymbolAddress((void**)&hb, g_h);

    cudaFuncSetAttribute(lstm_layer, cudaFuncAttributeMaxDynamicSharedMemorySize,
                         LSM_BYTES);

    dim3 gg(G4H / BN, M_ / BM);  // (32, 512)

    // Layer 0
    reset_bar<<<1, 1>>>();
    gemm_xw<<<gg, 256>>>(x, Wx0, xz);
    lstm_layer<<<NCTA, 256, LSM_BYTES>>>(xz, Wh0, b0,
                                         hb, hb + HB,
                                         y0,
                                         out + YSZ,            // h_final[0]
                                         out + YSZ + 2 * HB);  // c_final[0]

    // Layer 1 (reuse xz scratch)
    reset_bar<<<1, 1>>>();
    gemm_xw<<<gg, 256>>>(y0, Wx1, xz);
    lstm_layer<<<NCTA, 256, LSM_BYTES>>>(xz, Wh1, b1,
                                         hb + 2 * HB, hb + 3 * HB,
                                         out,
                                         out + YSZ + HB,       // h_final[1]
                                         out + YSZ + 3 * HB);  // c_final[1]
}

// round 6
// speedup vs baseline: 1.0743x; 1.0743x over previous
#include <cuda_runtime.h>
#include <cstdint>

typedef unsigned long long ull;

// Problem constants
#define B_   64
#define T_   1024
#define IN_  512
#define H_   512
#define G4H  2048
#define M_   (B_ * T_)                 // 65536 rows for the input GEMM
#define YSZ  ((size_t)B_ * T_ * H_)    // 33554432 y1 elements
#define HB   (H_ * B_)                 // 32768

// -------- scratch (static device globals; no allocation allowed) ----------
__device__ float g_xz[(size_t)M_ * G4H];   // xz for current layer [B,T,4H]
__device__ float g_y0[(size_t)M_ * H_];    // layer-0 output [B,T,H]
__device__ float g_h[2][2][HB];            // [layer][slot][k*64+m], h TRANSPOSED [H][B]
__device__ unsigned g_bar;                 // grid barrier counter

// -------- packed f32x2 helpers (Blackwell dual-fp32 pipe) -----------------
__device__ __forceinline__ ull ffma2(ull a, ull b, ull c) {
    ull d;
    asm("fma.rn.f32x2 %0, %1, %2, %3;" : "=l"(d) : "l"(a), "l"(b), "l"(c));
    return d;
}
__device__ __forceinline__ ull dup2(float x) {
    ull d;
    asm("mov.b64 %0, {%1, %1};" : "=l"(d) : "f"(x));
    return d;
}
__device__ __forceinline__ float2 unpk(ull v) {
    float lo, hi;
    asm("mov.b64 {%0, %1}, %2;" : "=f"(lo), "=f"(hi) : "l"(v));
    return make_float2(lo, hi);
}
// L2-coherent 16B load (bypass L1: h slots are rewritten by other SMs)
__device__ __forceinline__ void ldcg_u64x2(const void* p, ull& a, ull& b) {
    asm volatile("ld.global.cg.v2.u64 {%0, %1}, [%2];"
                 : "=l"(a), "=l"(b) : "l"(p));
}

// ===================== input-projection GEMM ==============================
// C[M,2048] = A[M,512] * W[512,2048]
// Pre-duplicated B tile (f32x2 pairs) + register double-buffering.
#define BM 128
#define BN 64
#define BK 16

__global__ __launch_bounds__(256, 2) void gemm_xw(const float* __restrict__ A,
                                                  const float* __restrict__ W,
                                                  float* __restrict__ C) {
    __shared__ float As[BK * BM];   // transposed A tile: As[k][m]      (8 KB)
    __shared__ ull   Bsd[BK * BN];  // Bsd[k][n] duplicated as f32x2    (8 KB)

    const int tid = threadIdx.x;
    const int tx = tid & 15;
    const int ty = tid >> 4;
    const int m0 = ty * 8;
    const int n0 = tx * 4;
    const long gm0 = (long)blockIdx.y * BM;
    const int  gn0 = blockIdx.x * BN;

    // staging indices
    const int ar0 = (tid * 2) >> 2;       // A row for j=0
    const int ak0 = (tid * 2) & 3;        // A k-quad for j=0
    const int ar1 = (tid * 2 + 1) >> 2;
    const int ak1 = (tid * 2 + 1) & 3;
    const int bkr = tid >> 4;             // B k-row
    const int bnq = tid & 15;             // B n-quad

    ull acc[4][4];
#pragma unroll
    for (int i = 0; i < 4; i++)
#pragma unroll
        for (int j = 0; j < 4; j++) acc[i][j] = 0ull;

    // --- stage k0 = 0 ---
    float4 a0 = *(const float4*)(A + (gm0 + ar0) * 512 + ak0 * 4);
    float4 a1 = *(const float4*)(A + (gm0 + ar1) * 512 + ak1 * 4);
    float4 bb = *(const float4*)(W + (long)bkr * G4H + gn0 + bnq * 4);
    {
        As[(ak0 * 4 + 0) * BM + ar0] = a0.x;
        As[(ak0 * 4 + 1) * BM + ar0] = a0.y;
        As[(ak0 * 4 + 2) * BM + ar0] = a0.z;
        As[(ak0 * 4 + 3) * BM + ar0] = a0.w;
        As[(ak1 * 4 + 0) * BM + ar1] = a1.x;
        As[(ak1 * 4 + 1) * BM + ar1] = a1.y;
        As[(ak1 * 4 + 2) * BM + ar1] = a1.z;
        As[(ak1 * 4 + 3) * BM + ar1] = a1.w;
        ull* bd = Bsd + bkr * BN + bnq * 4;
        bd[0] = dup2(bb.x); bd[1] = dup2(bb.y);
        bd[2] = dup2(bb.z); bd[3] = dup2(bb.w);
    }
    __syncthreads();

    for (int k0b = 0; k0b < 32; k0b++) {
        const int knext = (k0b + 1) * BK;
        if (k0b < 31) {   // prefetch next tile into regs (hidden under FMAs)
            a0 = *(const float4*)(A + (gm0 + ar0) * 512 + knext + ak0 * 4);
            a1 = *(const float4*)(A + (gm0 + ar1) * 512 + knext + ak1 * 4);
            bb = *(const float4*)(W + (long)(knext + bkr) * G4H + gn0 + bnq * 4);
        }

#pragma unroll
        for (int kk = 0; kk < BK; kk++) {
            const ull* ap = (const ull*)(As + kk * BM + m0);
            ull r0 = ap[0], r1 = ap[1], r2 = ap[2], r3 = ap[3];
            const ull* bp = Bsd + kk * BN + n0;
            ull b0 = bp[0], b1 = bp[1], b2 = bp[2], b3 = bp[3];
            acc[0][0] = ffma2(r0, b0, acc[0][0]);
            acc[0][1] = ffma2(r0, b1, acc[0][1]);
            acc[0][2] = ffma2(r0, b2, acc[0][2]);
            acc[0][3] = ffma2(r0, b3, acc[0][3]);
            acc[1][0] = ffma2(r1, b0, acc[1][0]);
            acc[1][1] = ffma2(r1, b1, acc[1][1]);
            acc[1][2] = ffma2(r1, b2, acc[1][2]);
            acc[1][3] = ffma2(r1, b3, acc[1][3]);
            acc[2][0] = ffma2(r2, b0, acc[2][0]);
            acc[2][1] = ffma2(r2, b1, acc[2][1]);
            acc[2][2] = ffma2(r2, b2, acc[2][2]);
            acc[2][3] = ffma2(r2, b3, acc[2][3]);
            acc[3][0] = ffma2(r3, b0, acc[3][0]);
            acc[3][1] = ffma2(r3, b1, acc[3][1]);
            acc[3][2] = ffma2(r3, b2, acc[3][2]);
            acc[3][3] = ffma2(r3, b3, acc[3][3]);
        }

        if (k0b < 31) {
            __syncthreads();   // all reads of current tile done
            As[(ak0 * 4 + 0) * BM + ar0] = a0.x;
            As[(ak0 * 4 + 1) * BM + ar0] = a0.y;
            As[(ak0 * 4 + 2) * BM + ar0] = a0.z;
            As[(ak0 * 4 + 3) * BM + ar0] = a0.w;
            As[(ak1 * 4 + 0) * BM + ar1] = a1.x;
            As[(ak1 * 4 + 1) * BM + ar1] = a1.y;
            As[(ak1 * 4 + 2) * BM + ar1] = a1.z;
            As[(ak1 * 4 + 3) * BM + ar1] = a1.w;
            ull* bd = Bsd + bkr * BN + bnq * 4;
            bd[0] = dup2(bb.x); bd[1] = dup2(bb.y);
            bd[2] = dup2(bb.z); bd[3] = dup2(bb.w);
            __syncthreads();
        }
    }

#pragma unroll
    for (int mp = 0; mp < 4; mp++) {
#pragma unroll
        for (int c = 0; c < 4; c++) {
            float2 v = unpk(acc[mp][c]);
            long row = gm0 + m0 + 2 * mp;
            C[row * G4H + gn0 + n0 + c]       = v.x;
            C[(row + 1) * G4H + gn0 + n0 + c] = v.y;
        }
    }
}

// ===================== persistent LSTM layer ==============================
// 128 CTAs (1/SM) x 256 threads. CTA j owns hidden units [4j,4j+4) = 16 gate
// columns. Thread GEMM tile = 16 cols x 4 batch rows, 16-way K split.
// h read from L2 (ld.cg) with 4-deep register pipeline; Wh slice cached in
// SMEM pre-duplicated as f32x2; c-state in registers.
#define PBS   66                                  // padded pbuf row stride
#define WD_BYTES (512 * 16 * 8)                   // 65536
#define PB_BYTES (16 * 16 * PBS * 4)              // 67584
#define LSM_BYTES (WD_BYTES + PB_BYTES)           // 133120
#define NCTA 128

__global__ __launch_bounds__(256, 1) void lstm_layer(
    const float* __restrict__ xz,     // [B,T,4H]
    const float* __restrict__ Wh,     // [512,2048]
    const float* __restrict__ bias,   // [2048]
    float* __restrict__ hs0,          // h slot 0, [H][B]
    float* __restrict__ hs1,          // h slot 1, [H][B]
    float* __restrict__ y,            // [B,T,H]
    float* __restrict__ hfin,         // [B,H]
    float* __restrict__ cfin)         // [B,H]
{
    extern __shared__ char smem[];
    ull*   wdup = (ull*)smem;                   // [512][16] duplicated Wh cols
    float* pbuf = (float*)(smem + WD_BYTES);    // [16 ks][16 c][PBS]

    const int tid = threadIdx.x;
    const int hu0 = blockIdx.x * 4;

    // ---- one-time: load this CTA's Wh slice, duplicated for f32x2 ----
    for (int idx = tid; idx < 512 * 16; idx += 256) {
        int k = idx >> 4, c = idx & 15;
        wdup[idx] = dup2(Wh[(long)k * G4H + (c >> 2) * 512 + hu0 + (c & 3)]);
    }

    // ---- roles ----
    const int mg = tid & 15;         // GEMM: 16 m-groups of 4 rows
    const int ks = tid >> 4;         // GEMM: 16-way K split (32 k each)
    const int m0 = mg * 4;
    const int m  = tid >> 2;         // gate pass: batch row
    const int u  = tid & 3;          // gate pass: local unit

    const float bi = bias[hu0 + u];
    const float bf = bias[512 + hu0 + u];
    const float bg = bias[1024 + hu0 + u];
    const float bo = bias[1536 + hu0 + u];
    float creg = 0.f;
    const float* xzp = xz + (size_t)m * T_ * G4H + hu0 + u;

    float* hslot[2] = { hs0, hs1 };
    __syncthreads();

    // prefetch xz for t = 0
    float x_i = xzp[0], x_f = xzp[512], x_g = xzp[1024], x_o = xzp[1536];

    for (int t = 0; t < T_; t++) {
        ull acc[2][16];
#pragma unroll
        for (int c = 0; c < 16; c++) { acc[0][c] = 0ull; acc[1][c] = 0ull; }

        if (t > 0) {
            const float* hin = hslot[(t + 1) & 1];   // slot written at t-1
            const float* hp  = hin + (ks * 32) * 64 + m0;
            const ull*   wr  = wdup + (ks * 32) * 16;

            // 4-deep h prefetch pipeline
            ull ph[4][2];
#pragma unroll
            for (int j = 0; j < 4; j++)
                ldcg_u64x2(hp + j * 64, ph[j][0], ph[j][1]);

#pragma unroll 8
            for (int k = 0; k < 32; k++) {
                ull h01 = ph[k & 3][0], h23 = ph[k & 3][1];
                if (k + 4 < 32)
                    ldcg_u64x2(hp + (k + 4) * 64, ph[k & 3][0], ph[k & 3][1]);
                const ulonglong2* w2 = (const ulonglong2*)(wr + k * 16);
                ulonglong2 w01 = w2[0], w23 = w2[1], w45 = w2[2], w67 = w2[3];
                ulonglong2 w89 = w2[4], wab = w2[5], wcd = w2[6], wef = w2[7];
                acc[0][0]  = ffma2(h01, w01.x, acc[0][0]);
                acc[1][0]  = ffma2(h23, w01.x, acc[1][0]);
                acc[0][1]  = ffma2(h01, w01.y, acc[0][1]);
                acc[1][1]  = ffma2(h23, w01.y, acc[1][1]);
                acc[0][2]  = ffma2(h01, w23.x, acc[0][2]);
                acc[1][2]  = ffma2(h23, w23.x, acc[1][2]);
                acc[0][3]  = ffma2(h01, w23.y, acc[0][3]);
                acc[1][3]  = ffma2(h23, w23.y, acc[1][3]);
                acc[0][4]  = ffma2(h01, w45.x, acc[0][4]);
                acc[1][4]  = ffma2(h23, w45.x, acc[1][4]);
                acc[0][5]  = ffma2(h01, w45.y, acc[0][5]);
                acc[1][5]  = ffma2(h23, w45.y, acc[1][5]);
                acc[0][6]  = ffma2(h01, w67.x, acc[0][6]);
                acc[1][6]  = ffma2(h23, w67.x, acc[1][6]);
                acc[0][7]  = ffma2(h01, w67.y, acc[0][7]);
                acc[1][7]  = ffma2(h23, w67.y, acc[1][7]);
                acc[0][8]  = ffma2(h01, w89.x, acc[0][8]);
                acc[1][8]  = ffma2(h23, w89.x, acc[1][8]);
                acc[0][9]  = ffma2(h01, w89.y, acc[0][9]);
                acc[1][9]  = ffma2(h23, w89.y, acc[1][9]);
                acc[0][10] = ffma2(h01, wab.x, acc[0][10]);
                acc[1][10] = ffma2(h23, wab.x, acc[1][10]);
                acc[0][11] = ffma2(h01, wab.y, acc[0][11]);
                acc[1][11] = ffma2(h23, wab.y, acc[1][11]);
                acc[0][12] = ffma2(h01, wcd.x, acc[0][12]);
                acc[1][12] = ffma2(h23, wcd.x, acc[1][12]);
                acc[0][13] = ffma2(h01, wcd.y, acc[0][13]);
                acc[1][13] = ffma2(h23, wcd.y, acc[1][13]);
                acc[0][14] = ffma2(h01, wef.x, acc[0][14]);
                acc[1][14] = ffma2(h23, wef.x, acc[1][14]);
                acc[0][15] = ffma2(h01, wef.y, acc[0][15]);
                acc[1][15] = ffma2(h23, wef.y, acc[1][15]);
            }
        }

        __syncthreads();   // previous step's pbuf reads are done
#pragma unroll
        for (int c = 0; c < 16; c++) {
            *(ull*)&pbuf[(ks * 16 + c) * PBS + m0]     = acc[0][c];
            *(ull*)&pbuf[(ks * 16 + c) * PBS + m0 + 2] = acc[1][c];
        }
        __syncthreads();

        // ---- K-split reduction + gates (thread = (m, u)) ----
        float zi = bi + x_i, zf = bf + x_f, zg = bg + x_g, zo = bo + x_o;
#pragma unroll
        for (int s = 0; s < 16; s++) {
            const float* pr = pbuf + (s * 16 + u) * PBS + m;
            zi += pr[0];
            zf += pr[4 * PBS];
            zg += pr[8 * PBS];
            zo += pr[12 * PBS];
        }

        float ig  = 1.f / (1.f + __expf(-zi));
        float fg  = 1.f / (1.f + __expf(-zf));
        float gg  = tanhf(zg);
        float ogt = 1.f / (1.f + __expf(-zo));

        creg = fg * creg + ig * gg;
        float hn = ogt * tanhf(creg);

        hslot[t & 1][(hu0 + u) * 64 + m] = hn;
        y[((size_t)m * T_ + t) * H_ + hu0 + u] = hn;

        if (t == T_ - 1) {
            hfin[m * H_ + hu0 + u] = hn;
            cfin[m * H_ + hu0 + u] = creg;
        } else {
            // grid barrier: arrive (release) -> prefetch xz(t+1) -> wait
            __syncthreads();   // all h stores of this CTA issued
            if (tid == 0)
                asm volatile("red.release.gpu.global.add.u32 [%0], %1;"
                             :: "l"(&g_bar), "r"(1u) : "memory");
            const float* xp = xzp + (size_t)(t + 1) * G4H;
            x_i = xp[0]; x_f = xp[512]; x_g = xp[1024]; x_o = xp[1536];
            if (tid == 0) {
                unsigned target = (unsigned)(t + 1) * NCTA, v;
                do {
                    asm volatile("ld.acquire.gpu.global.u32 %0, [%1];"
                                 : "=r"(v) : "l"(&g_bar) : "memory");
                } while (v < target);
            }
            __syncthreads();
        }
    }
}

// ===================== launch =============================================
extern "C" void kernel_launch(void* const* d_in, const int* in_sizes, int n_in,
                              void* d_out, int out_size) {
    const float* x   = (const float*)d_in[0];
    const float* Wx0 = (const float*)d_in[1];
    const float* Wh0 = (const float*)d_in[2];
    const float* b0  = (const float*)d_in[3];
    const float* Wx1 = (const float*)d_in[4];
    const float* Wh1 = (const float*)d_in[5];
    const float* b1  = (const float*)d_in[6];
    float* out = (float*)d_out;

    float *xz, *y0, *hb;
    unsigned* barp;
    cudaGetSymbolAddress((void**)&xz, g_xz);
    cudaGetSymbolAddress((void**)&y0, g_y0);
    cudaGetSymbolAddress((void**)&hb, g_h);
    cudaGetSymbolAddress((void**)&barp, g_bar);

    cudaFuncSetAttribute(lstm_layer, cudaFuncAttributeMaxDynamicSharedMemorySize,
                         LSM_BYTES);

    dim3 gg(G4H / BN, M_ / BM);  // (32, 512)

    // Layer 0
    cudaMemsetAsync(barp, 0, sizeof(unsigned));
    gemm_xw<<<gg, 256>>>(x, Wx0, xz);
    lstm_layer<<<NCTA, 256, LSM_BYTES>>>(xz, Wh0, b0,
                                         hb, hb + HB,
                                         y0,
                                         out + YSZ,            // h_final[0]
                                         out + YSZ + 2 * HB);  // c_final[0]

    // Layer 1 (reuse xz scratch)
    cudaMemsetAsync(barp, 0, sizeof(unsigned));
    gemm_xw<<<gg, 256>>>(y0, Wx1, xz);
    lstm_layer<<<NCTA, 256, LSM_BYTES>>>(xz, Wh1, b1,
                                         hb + 2 * HB, hb + 3 * HB,
                                         out,
                                         out + YSZ + HB,       // h_final[1]
                                         out + YSZ + 3 * HB);  // c_final[1]
}